// round 3
// baseline (speedup 1.0000x reference)
#include <cuda_runtime.h>

#define HIDDEN 2048
#define INTER  1408
#define TOPK   6

// Scratch for the intermediate activations (silu(gate)*up), 6*1408 floats = 33 KB.
__device__ float g_inter[TOPK * INTER];

// ---------------------------------------------------------------------------
// Kernel 1: inter[k][i] = silu(gate) * up
//   gate = dot(GU[e_k][i      ][:], x)   (2048-wide)
//   up   = dot(GU[e_k][i+INTER][:], x)
// One 256-thread block per (i, k). Coalesced float4 streaming of both rows.
// ---------------------------------------------------------------------------
__global__ void __launch_bounds__(256, 8)
gate_up_silu_kernel(const float* __restrict__ x,
                    const int* __restrict__ topk_idx,
                    const float* __restrict__ gu_all)
{
    const int i = blockIdx.x;          // 0..INTER-1
    const int k = blockIdx.y;          // 0..TOPK-1
    const int t = threadIdx.x;

    const int e = topk_idx[k];
    const size_t base = ((size_t)e * (2 * INTER) + i) * HIDDEN;

    const float4* __restrict__ xg = (const float4*)x;
    const float4* __restrict__ gr = (const float4*)(gu_all + base);
    const float4* __restrict__ ur = (const float4*)(gu_all + base + (size_t)INTER * HIDDEN);

    float gs = 0.f, us = 0.f;
    // HIDDEN/4 = 512 float4; 256 threads -> exactly 2 iters each.
    #pragma unroll
    for (int j = t; j < HIDDEN / 4; j += 256) {
        float4 xv = xg[j];
        float4 gv = gr[j];
        float4 uv = ur[j];
        gs += xv.x * gv.x + xv.y * gv.y + xv.z * gv.z + xv.w * gv.w;
        us += xv.x * uv.x + xv.y * uv.y + xv.z * uv.z + xv.w * uv.w;
    }

    // warp reduce
    #pragma unroll
    for (int off = 16; off > 0; off >>= 1) {
        gs += __shfl_down_sync(0xffffffff, gs, off);
        us += __shfl_down_sync(0xffffffff, us, off);
    }

    __shared__ float sg[8], su[8];
    const int wid = t >> 5, lid = t & 31;
    if (lid == 0) { sg[wid] = gs; su[wid] = us; }
    __syncthreads();

    if (t == 0) {
        float G = 0.f, U = 0.f;
        #pragma unroll
        for (int w = 0; w < 8; ++w) { G += sg[w]; U += su[w]; }
        // silu(G) * U
        float s = G / (1.0f + expf(-G));
        g_inter[k * INTER + i] = s * U;
    }
}

// ---------------------------------------------------------------------------
// Kernel 2: out[h] = sum_k w[k] * dot(down[e_k][h][:], inter[k][:])
// One 128-thread block per h. Down rows are 1408-wide (352 float4), streamed
// coalesced; inter vector hits L2. No atomics -> deterministic.
// ---------------------------------------------------------------------------
__global__ void __launch_bounds__(128, 8)
down_kernel(const int* __restrict__ topk_idx,
            const float* __restrict__ topk_w,
            const float* __restrict__ down_all,
            float* __restrict__ out)
{
    const int h = blockIdx.x;          // 0..HIDDEN-1
    const int t = threadIdx.x;

    float acc = 0.f;
    #pragma unroll
    for (int k = 0; k < TOPK; ++k) {
        const int e = topk_idx[k];
        const float wk = topk_w[k];
        const float4* __restrict__ dr =
            (const float4*)(down_all + ((size_t)e * HIDDEN + h) * INTER);
        const float4* __restrict__ iv = (const float4*)(g_inter + k * INTER);

        float d = 0.f;
        // INTER/4 = 352 float4; 128 threads -> up to 3 iters each.
        for (int j = t; j < INTER / 4; j += 128) {
            float4 dv = dr[j];
            float4 vv = iv[j];
            d += dv.x * vv.x + dv.y * vv.y + dv.z * vv.z + dv.w * vv.w;
        }
        acc += wk * d;
    }

    // warp reduce
    #pragma unroll
    for (int off = 16; off > 0; off >>= 1)
        acc += __shfl_down_sync(0xffffffff, acc, off);

    __shared__ float sa[4];
    const int wid = t >> 5, lid = t & 31;
    if (lid == 0) sa[wid] = acc;
    __syncthreads();

    if (t == 0)
        out[h] = sa[0] + sa[1] + sa[2] + sa[3];
}

// ---------------------------------------------------------------------------
extern "C" void kernel_launch(void* const* d_in, const int* in_sizes, int n_in,
                              void* d_out, int out_size)
{
    const float* x        = (const float*)d_in[0];      // [1,2048,1,1]
    const int*   topk_idx = (const int*)d_in[1];        // [6] (int32 — JAX x64 disabled)
    const float* topk_w   = (const float*)d_in[2];      // [6]
    const float* gu_all   = (const float*)d_in[3];      // [60, 2816, 2048]
    const float* down_all = (const float*)d_in[4];      // [60, 2048, 1408]
    float*       out      = (float*)d_out;              // [2048]

    dim3 grid1(INTER, TOPK);
    gate_up_silu_kernel<<<grid1, 256>>>(x, topk_idx, gu_all);

    down_kernel<<<HIDDEN, 128>>>(topk_idx, topk_w, down_all, out);
}